// round 2
// baseline (speedup 1.0000x reference)
#include <cuda_runtime.h>
#include <math.h>

// Problem constants
#define MROWS 81920          // BV*HW = 20*4096  (== B*L = 4*20480)
#define CDIM  256
#define LB    20480          // rows per batch n
#define HN    8
#define DH    32
#define NBATCH 4
#define TILES 160            // L-tiles of 128 per batch
#define TM 128
#define TK 32

// Scratch (static __device__ — no allocation allowed)
__device__ float g_q   [MROWS * CDIM];                 // elu(q)+1
__device__ float g_y   [MROWS * CDIM];                 // y before proj
__device__ float g_kvp [NBATCH * TILES * HN * DH * DH]; // per-tile kv partials
__device__ float g_ksp [NBATCH * TILES * HN * DH];      // per-tile k_sum partials
__device__ float g_kv  [NBATCH * HN * DH * DH];
__device__ float g_ksum[NBATCH * HN * DH];

// ---------------------------------------------------------------------------
// k1: per (head, L-tile of 128 rows): qkv GEMM slice (128 x 96), elu+1 on q,k,
//     q -> g_q, then per-tile kv = V^T K (32x32) and k_sum partials.
// ---------------------------------------------------------------------------
__global__ __launch_bounds__(256) void k1_qkv(const float* __restrict__ x,
                                              const float* __restrict__ Wqkv)
{
    __shared__ float sm[8448];
    const int h    = blockIdx.x;        // 0..7
    const int tile = blockIdx.y;        // 0..639
    const int tid  = threadIdx.x;
    const int ty   = tid >> 4, tx = tid & 15;
    const int row0 = ty * 8, col0 = tx * 6;
    const long mbase = (long)tile * TM;

    float acc[8][6];
    #pragma unroll
    for (int i = 0; i < 8; i++)
        #pragma unroll
        for (int j = 0; j < 6; j++) acc[i][j] = 0.f;

    float* xs = sm;          // [32][132] k-major x tile
    float* ws = sm + 4224;   // [32][100] k-major W slice (96 cols: q|k|v of head h)

    for (int kb = 0; kb < CDIM; kb += TK) {
        #pragma unroll
        for (int it = 0; it < 4; ++it) {
            int idx = tid + it * 256;          // 0..1023, 8 float4 per row
            int r = idx >> 3, c4 = idx & 7;
            float4 v = *(const float4*)(x + (mbase + r) * CDIM + kb + c4 * 4);
            xs[(c4 * 4 + 0) * 132 + r] = v.x;
            xs[(c4 * 4 + 1) * 132 + r] = v.y;
            xs[(c4 * 4 + 2) * 132 + r] = v.z;
            xs[(c4 * 4 + 3) * 132 + r] = v.w;
        }
        #pragma unroll
        for (int it = 0; it < 3; ++it) {
            int idx = tid + it * 256;          // 0..767, 24 float4 per k-row
            int r = idx / 24, c4 = idx % 24;
            int j = c4 * 4;
            int part = j >> 5, jj = j & 31;    // 0=q,1=k,2=v
            float4 v = *(const float4*)(Wqkv + (kb + r) * 768 + part * 256 + h * 32 + jj);
            ws[r * 100 + j    ] = v.x;
            ws[r * 100 + j + 1] = v.y;
            ws[r * 100 + j + 2] = v.z;
            ws[r * 100 + j + 3] = v.w;
        }
        __syncthreads();
        #pragma unroll 8
        for (int kk = 0; kk < TK; ++kk) {
            float a[8], b[6];
            #pragma unroll
            for (int i = 0; i < 8; i++) a[i] = xs[kk * 132 + row0 + i];
            #pragma unroll
            for (int j = 0; j < 6; j++) b[j] = ws[kk * 100 + col0 + j];
            #pragma unroll
            for (int i = 0; i < 8; i++)
                #pragma unroll
                for (int j = 0; j < 6; j++) acc[i][j] += a[i] * b[j];
        }
        __syncthreads();
    }

    // Epilogue: elu+1, q -> global, k/v -> smem (reuse sm; synced above)
    float* ks = sm;             // [128][32]
    float* vs = sm + 4096;      // [128][32]
    #pragma unroll
    for (int jl = 0; jl < 6; jl++) {
        int j = col0 + jl;
        int part = j >> 5, jj = j & 31;
        #pragma unroll
        for (int i = 0; i < 8; i++) {
            int r = row0 + i;
            float val = acc[i][jl];
            if (part == 0) {
                val = (val > 0.f) ? (val + 1.f) : expf(val);
                g_q[(mbase + r) * CDIM + h * 32 + jj] = val;
            } else if (part == 1) {
                val = (val > 0.f) ? (val + 1.f) : expf(val);
                ks[r * 32 + jj] = val;
            } else {
                vs[r * 32 + jj] = val;
            }
        }
    }
    __syncthreads();

    // Partial kv[m][d] = sum_l vs[l][m] * ks[l][d]  (each thread: 1 m, 4 d)
    const int m  = tid >> 3;
    const int dd = (tid & 7) * 4;
    float s0 = 0.f, s1 = 0.f, s2 = 0.f, s3 = 0.f;
    for (int l = 0; l < 128; l++) {
        float  vv = vs[l * 32 + m];
        float4 k4 = *(const float4*)&ks[l * 32 + dd];
        s0 += vv * k4.x; s1 += vv * k4.y; s2 += vv * k4.z; s3 += vv * k4.w;
    }
    long pb = (((long)tile * HN + h) * DH + m) * DH + dd;
    g_kvp[pb] = s0; g_kvp[pb + 1] = s1; g_kvp[pb + 2] = s2; g_kvp[pb + 3] = s3;

    if (tid < 32) {
        float s = 0.f;
        for (int l = 0; l < 128; l++) s += ks[l * 32 + tid];
        g_ksp[((long)tile * HN + h) * DH + tid] = s;
    }
}

// ---------------------------------------------------------------------------
// k_reduce: fixed-order (deterministic) reduction of tile partials per (n,h)
// ---------------------------------------------------------------------------
__global__ __launch_bounds__(1024) void k_reduce()
{
    const int n = blockIdx.x, h = blockIdx.y;
    const int tid = threadIdx.x;  // 0..1023 (= m*32+d)
    float s = 0.f;
    for (int t = 0; t < TILES; t++)
        s += g_kvp[(((long)(n * TILES + t) * HN + h) * 1024) + tid];
    g_kv[(n * HN + h) * 1024 + tid] = s;
    if (tid < 32) {
        float s2 = 0.f;
        for (int t = 0; t < TILES; t++)
            s2 += g_ksp[((long)(n * TILES + t) * HN + h) * 32 + tid];
        g_ksum[(n * HN + h) * 32 + tid] = s2;
    }
}

// ---------------------------------------------------------------------------
// k2: y[l,h,m] = z * sum_d q[l,h,d]*kv[n,h,m,d],  z = 1/(q . k_sum + eps)
//     Block = 256 rows of one batch; per head: stage q rows through smem.
// ---------------------------------------------------------------------------
__global__ __launch_bounds__(256) void k2_y()
{
    __shared__ float qs[256 * 33];
    __shared__ float kvh[1024];
    __shared__ float ksh[32];
    const int tid  = threadIdx.x;
    const long base = (long)blockIdx.x * 256;
    const int n    = (int)(base / LB);

    for (int h = 0; h < HN; ++h) {
        __syncthreads();  // guard smem reuse from previous head
        #pragma unroll
        for (int it = 0; it < 4; ++it)
            kvh[tid + it * 256] = g_kv[(n * HN + h) * 1024 + tid + it * 256];
        if (tid < 32) ksh[tid] = g_ksum[(n * HN + h) * 32 + tid];
        #pragma unroll
        for (int it = 0; it < 32; ++it) {
            int idx = tid + it * 256;
            int r = idx >> 5, d = idx & 31;
            qs[r * 33 + d] = g_q[(base + r) * CDIM + h * 32 + d];
        }
        __syncthreads();

        float qh[32];
        #pragma unroll
        for (int d = 0; d < 32; ++d) qh[d] = qs[tid * 33 + d];

        float zacc = 1e-6f;
        #pragma unroll
        for (int d = 0; d < 32; ++d) zacc += qh[d] * ksh[d];
        const float z = 1.f / zacc;

        float yv[32];
        #pragma unroll
        for (int mp = 0; mp < 32; ++mp) {
            float s = 0.f;
            #pragma unroll
            for (int d = 0; d < 32; ++d) s += qh[d] * kvh[mp * 32 + d];
            yv[mp] = s * z;
        }

        __syncthreads();
        #pragma unroll
        for (int mp = 0; mp < 32; ++mp) qs[tid * 33 + mp] = yv[mp];
        __syncthreads();
        #pragma unroll
        for (int it = 0; it < 32; ++it) {
            int idx = tid + it * 256;
            int r = idx >> 5, d = idx & 31;
            g_y[(base + r) * CDIM + h * 32 + d] = qs[r * 33 + d];
        }
    }
}

// ---------------------------------------------------------------------------
// k3: out = y @ W_proj + b_proj    (128x64 tiles, TK=32)
// ---------------------------------------------------------------------------
__global__ __launch_bounds__(256) void k3_proj(const float* __restrict__ Wp,
                                               const float* __restrict__ bp,
                                               float* __restrict__ out)
{
    __shared__ float sm[4224 + 2176];
    float* as_ = sm;          // [32][132]
    float* bs_ = sm + 4224;   // [32][68]
    const int tile = blockIdx.x;   // 0..639
    const int nt   = blockIdx.y;   // 0..3
    const int tid  = threadIdx.x;
    const int ty = tid >> 4, tx = tid & 15;
    const int row0 = ty * 8, col0 = tx * 4;
    const long mbase = (long)tile * TM;

    float acc[8][4];
    #pragma unroll
    for (int i = 0; i < 8; i++)
        #pragma unroll
        for (int j = 0; j < 4; j++) acc[i][j] = 0.f;

    for (int kb = 0; kb < CDIM; kb += TK) {
        #pragma unroll
        for (int it = 0; it < 4; ++it) {
            int idx = tid + it * 256;
            int r = idx >> 3, c4 = idx & 7;
            float4 v = *(const float4*)(g_y + (mbase + r) * CDIM + kb + c4 * 4);
            as_[(c4 * 4 + 0) * 132 + r] = v.x;
            as_[(c4 * 4 + 1) * 132 + r] = v.y;
            as_[(c4 * 4 + 2) * 132 + r] = v.z;
            as_[(c4 * 4 + 3) * 132 + r] = v.w;
        }
        #pragma unroll
        for (int it = 0; it < 2; ++it) {
            int idx = tid + it * 256;          // 0..511, 16 float4 per k-row
            int r = idx >> 4, c4 = idx & 15;
            float4 v = *(const float4*)(Wp + (kb + r) * CDIM + nt * 64 + c4 * 4);
            bs_[r * 68 + c4 * 4    ] = v.x;
            bs_[r * 68 + c4 * 4 + 1] = v.y;
            bs_[r * 68 + c4 * 4 + 2] = v.z;
            bs_[r * 68 + c4 * 4 + 3] = v.w;
        }
        __syncthreads();
        #pragma unroll 8
        for (int kk = 0; kk < TK; ++kk) {
            float a[8];
            #pragma unroll
            for (int i = 0; i < 8; i++) a[i] = as_[kk * 132 + row0 + i];
            float4 b4 = *(const float4*)&bs_[kk * 68 + col0];
            #pragma unroll
            for (int i = 0; i < 8; i++) {
                acc[i][0] += a[i] * b4.x;
                acc[i][1] += a[i] * b4.y;
                acc[i][2] += a[i] * b4.z;
                acc[i][3] += a[i] * b4.w;
            }
        }
        __syncthreads();
    }

    float4 bb = *(const float4*)(bp + nt * 64 + col0);
    #pragma unroll
    for (int i = 0; i < 8; i++) {
        float4 o;
        o.x = acc[i][0] + bb.x;
        o.y = acc[i][1] + bb.y;
        o.z = acc[i][2] + bb.z;
        o.w = acc[i][3] + bb.w;
        *(float4*)(out + (mbase + row0 + i) * CDIM + nt * 64 + col0) = o;
    }
}

// ---------------------------------------------------------------------------
extern "C" void kernel_launch(void* const* d_in, const int* in_sizes, int n_in,
                              void* d_out, int out_size)
{
    const float* x     = (const float*)d_in[0];
    const float* Wqkv  = (const float*)d_in[1];
    const float* Wproj = (const float*)d_in[2];
    const float* bproj = (const float*)d_in[3];
    float* out = (float*)d_out;

    dim3 g1(HN, MROWS / TM);           // (8, 640)
    k1_qkv<<<g1, 256>>>(x, Wqkv);

    dim3 g2(NBATCH, HN);               // (4, 8)
    k_reduce<<<g2, 1024>>>();

    k2_y<<<MROWS / 256, 256>>>();      // 320 blocks

    dim3 g3(MROWS / TM, 4);            // (640, 4)
    k3_proj<<<g3, 256>>>(Wproj, bproj, out);
}

// round 3
// speedup vs baseline: 2.0949x; 2.0949x over previous
#include <cuda_runtime.h>
#include <math.h>

// Problem constants
#define MROWS 81920          // BV*HW = 20*4096  (== B*L = 4*20480)
#define CDIM  256
#define LB    20480          // rows per batch n
#define HN    8
#define DH    32
#define NBATCH 4
#define TILES 160            // L-tiles of 128 per batch
#define TM 128
#define TK 32

// Scratch (static __device__ — no allocation allowed)
__device__ float g_q   [MROWS * CDIM];                  // elu(q)+1
__device__ float g_y   [MROWS * CDIM];                  // y before proj
__device__ float g_kvp [NBATCH * TILES * HN * DH * DH]; // per-tile kv partials
__device__ float g_ksp [NBATCH * TILES * HN * DH];      // per-tile k_sum partials
__device__ float g_kv  [NBATCH * HN * DH * DH];
__device__ float g_ksum[NBATCH * HN * DH];

__device__ __forceinline__ unsigned f2tf(float f) {
    unsigned u;
    asm("cvt.rna.tf32.f32 %0, %1;" : "=r"(u) : "f"(f));
    return u;
}

__device__ __forceinline__ void mma_tf32(float* c, const unsigned* a, const unsigned* b) {
    asm volatile(
        "mma.sync.aligned.m16n8k8.row.col.f32.tf32.tf32.f32 "
        "{%0,%1,%2,%3}, {%4,%5,%6,%7}, {%8,%9}, {%0,%1,%2,%3};\n"
        : "+f"(c[0]), "+f"(c[1]), "+f"(c[2]), "+f"(c[3])
        : "r"(a[0]), "r"(a[1]), "r"(a[2]), "r"(a[3]), "r"(b[0]), "r"(b[1]));
}

// ---------------------------------------------------------------------------
// k1: per (head, L-tile of 128 rows): qkv GEMM slice (128 x 96) via TF32 MMA,
//     elu+1 on q,k; q -> g_q; per-tile kv = V^T K (32x32) and k_sum partials.
// ---------------------------------------------------------------------------
__global__ __launch_bounds__(256) void k1_qkv(const float* __restrict__ x,
                                              const float* __restrict__ Wqkv)
{
    __shared__ float sm[8192];                      // 32 KB, multi-purpose
    unsigned* As = (unsigned*)sm;                   // [128][36] row-major (m,k)
    unsigned* Bs = (unsigned*)(sm + 4608);          // [32][104] k-major  (k,n)

    const int h    = blockIdx.x;        // 0..7
    const int tile = blockIdx.y;        // 0..639
    const int tid  = threadIdx.x;
    const int warp = tid >> 5, lane = tid & 31;
    const int wm = warp >> 1, wn = warp & 1;        // 4 x 2 warp grid
    const int rb = wm * 32, cb = wn * 48;           // warp tile 32 x 48
    const int g  = lane >> 2, tg = lane & 3;
    const long mbase = (long)tile * TM;

    float acc[2][6][4];
    #pragma unroll
    for (int mt = 0; mt < 2; mt++)
        #pragma unroll
        for (int nt = 0; nt < 6; nt++)
            #pragma unroll
            for (int e = 0; e < 4; e++) acc[mt][nt][e] = 0.f;

    for (int kb = 0; kb < CDIM; kb += TK) {
        // Load A tile (128 x 32 of x), convert tf32, row-major stride 36
        #pragma unroll
        for (int it = 0; it < 4; ++it) {
            int idx = tid + it * 256;              // 0..1023
            int r = idx >> 3, c4 = idx & 7;
            float4 v = *(const float4*)(x + (mbase + r) * CDIM + kb + c4 * 4);
            uint4 u = { f2tf(v.x), f2tf(v.y), f2tf(v.z), f2tf(v.w) };
            *(uint4*)&As[r * 36 + c4 * 4] = u;
        }
        // Load B tile (32 x 96 of Wqkv head slice), k-major stride 104
        #pragma unroll
        for (int it = 0; it < 3; ++it) {
            int idx = tid + it * 256;              // 0..767
            int r = idx / 24, c4 = idx % 24;
            int j = c4 * 4;
            int part = j >> 5, jj = j & 31;
            float4 v = *(const float4*)(Wqkv + (kb + r) * 768 + part * 256 + h * 32 + jj);
            uint4 u = { f2tf(v.x), f2tf(v.y), f2tf(v.z), f2tf(v.w) };
            *(uint4*)&Bs[r * 104 + j] = u;
        }
        __syncthreads();

        #pragma unroll
        for (int ks = 0; ks < TK; ks += 8) {
            unsigned a[2][4], b[6][2];
            #pragma unroll
            for (int mt = 0; mt < 2; mt++) {
                int base = (rb + mt * 16 + g) * 36 + ks + tg;
                a[mt][0] = As[base];
                a[mt][1] = As[base + 8 * 36];
                a[mt][2] = As[base + 4];
                a[mt][3] = As[base + 8 * 36 + 4];
            }
            #pragma unroll
            for (int nt = 0; nt < 6; nt++) {
                int col = cb + nt * 8 + g;
                b[nt][0] = Bs[(ks + tg) * 104 + col];
                b[nt][1] = Bs[(ks + tg + 4) * 104 + col];
            }
            #pragma unroll
            for (int mt = 0; mt < 2; mt++)
                #pragma unroll
                for (int nt = 0; nt < 6; nt++)
                    mma_tf32(acc[mt][nt], a[mt], b[nt]);
        }
        __syncthreads();
    }

    // Epilogue: elu+1 on q,k; q -> global; k,v -> smem
    float* ksm = sm;            // [128][32]
    float* vsm = sm + 4096;     // [128][32]
    #pragma unroll
    for (int mt = 0; mt < 2; mt++)
        #pragma unroll
        for (int nt = 0; nt < 6; nt++)
            #pragma unroll
            for (int e = 0; e < 4; e++) {
                int r = rb + mt * 16 + g + ((e >= 2) ? 8 : 0);
                int c = cb + nt * 8 + tg * 2 + (e & 1);
                float val = acc[mt][nt][e];
                int part = c >> 5, jj = c & 31;
                if (part == 0) {
                    val = (val > 0.f) ? (val + 1.f) : expf(val);
                    g_q[(mbase + r) * CDIM + h * 32 + jj] = val;
                } else if (part == 1) {
                    val = (val > 0.f) ? (val + 1.f) : expf(val);
                    ksm[r * 32 + jj] = val;
                } else {
                    vsm[r * 32 + jj] = val;
                }
            }
    __syncthreads();

    // Partial kv[m][d] = sum_l vsm[l][m] * ksm[l][d]  (each thread: 1 m, 4 d)
    const int m  = tid >> 3;
    const int dd = (tid & 7) * 4;
    float s0 = 0.f, s1 = 0.f, s2 = 0.f, s3 = 0.f;
    for (int l = 0; l < 128; l++) {
        float  vv = vsm[l * 32 + m];
        float4 k4 = *(const float4*)&ksm[l * 32 + dd];
        s0 += vv * k4.x; s1 += vv * k4.y; s2 += vv * k4.z; s3 += vv * k4.w;
    }
    long pb = (((long)tile * HN + h) * DH + m) * DH + dd;
    g_kvp[pb] = s0; g_kvp[pb + 1] = s1; g_kvp[pb + 2] = s2; g_kvp[pb + 3] = s3;

    if (tid < 32) {
        float s = 0.f;
        for (int l = 0; l < 128; l++) s += ksm[l * 32 + tid];
        g_ksp[((long)tile * HN + h) * DH + tid] = s;
    }
}

// ---------------------------------------------------------------------------
// k_reduce: fixed-order (deterministic) reduction of tile partials per (n,h)
// ---------------------------------------------------------------------------
__global__ __launch_bounds__(1024) void k_reduce()
{
    const int n = blockIdx.x, h = blockIdx.y;
    const int tid = threadIdx.x;  // 0..1023 (= m*32+d)
    float s = 0.f;
    for (int t = 0; t < TILES; t++)
        s += g_kvp[(((long)(n * TILES + t) * HN + h) * 1024) + tid];
    g_kv[(n * HN + h) * 1024 + tid] = s;
    if (tid < 32) {
        float s2 = 0.f;
        for (int t = 0; t < TILES; t++)
            s2 += g_ksp[((long)(n * TILES + t) * HN + h) * 32 + tid];
        g_ksum[(n * HN + h) * 32 + tid] = s2;
    }
}

// ---------------------------------------------------------------------------
// k2: y[l,h,m] = z * sum_d q[l,h,d]*kv[n,h,m,d],  z = 1/(q . k_sum + eps)
// ---------------------------------------------------------------------------
__global__ __launch_bounds__(256) void k2_y()
{
    __shared__ float qs[256 * 33];
    __shared__ float kvh[1024];
    __shared__ float ksh[32];
    const int tid  = threadIdx.x;
    const long base = (long)blockIdx.x * 256;
    const int n    = (int)(base / LB);

    for (int h = 0; h < HN; ++h) {
        __syncthreads();
        #pragma unroll
        for (int it = 0; it < 4; ++it)
            kvh[tid + it * 256] = g_kv[(n * HN + h) * 1024 + tid + it * 256];
        if (tid < 32) ksh[tid] = g_ksum[(n * HN + h) * 32 + tid];
        #pragma unroll
        for (int it = 0; it < 32; ++it) {
            int idx = tid + it * 256;
            int r = idx >> 5, d = idx & 31;
            qs[r * 33 + d] = g_q[(base + r) * CDIM + h * 32 + d];
        }
        __syncthreads();

        float qh[32];
        #pragma unroll
        for (int d = 0; d < 32; ++d) qh[d] = qs[tid * 33 + d];

        float zacc = 1e-6f;
        #pragma unroll
        for (int d = 0; d < 32; ++d) zacc += qh[d] * ksh[d];
        const float z = 1.f / zacc;

        float yv[32];
        #pragma unroll
        for (int mp = 0; mp < 32; ++mp) {
            float s = 0.f;
            #pragma unroll
            for (int d = 0; d < 32; ++d) s += qh[d] * kvh[mp * 32 + d];
            yv[mp] = s * z;
        }

        __syncthreads();
        #pragma unroll
        for (int mp = 0; mp < 32; ++mp) qs[tid * 33 + mp] = yv[mp];
        __syncthreads();
        #pragma unroll
        for (int it = 0; it < 32; ++it) {
            int idx = tid + it * 256;
            int r = idx >> 5, d = idx & 31;
            g_y[(base + r) * CDIM + h * 32 + d] = qs[r * 33 + d];
        }
    }
}

// ---------------------------------------------------------------------------
// k3: out = y @ W_proj + b_proj via TF32 MMA. 128x128 tiles, grid (640, 2).
// ---------------------------------------------------------------------------
__global__ __launch_bounds__(256) void k3_proj(const float* __restrict__ Wp,
                                               const float* __restrict__ bp,
                                               float* __restrict__ out)
{
    __shared__ float sm[8960];                      // 35 KB
    unsigned* As = (unsigned*)sm;                   // [128][36] row-major
    unsigned* Bs = (unsigned*)(sm + 4608);          // [32][136] k-major

    const int tile = blockIdx.x;   // 0..639
    const int nblk = blockIdx.y;   // 0..1 (128 cols each)
    const int tid  = threadIdx.x;
    const int warp = tid >> 5, lane = tid & 31;
    const int wm = warp >> 1, wn = warp & 1;        // 4 x 2 warp grid
    const int rb = wm * 32, cb = wn * 64;           // warp tile 32 x 64
    const int g  = lane >> 2, tg = lane & 3;
    const long mbase = (long)tile * TM;

    float acc[2][8][4];
    #pragma unroll
    for (int mt = 0; mt < 2; mt++)
        #pragma unroll
        for (int nt = 0; nt < 8; nt++)
            #pragma unroll
            for (int e = 0; e < 4; e++) acc[mt][nt][e] = 0.f;

    for (int kb = 0; kb < CDIM; kb += TK) {
        #pragma unroll
        for (int it = 0; it < 4; ++it) {
            int idx = tid + it * 256;
            int r = idx >> 3, c4 = idx & 7;
            float4 v = *(const float4*)(g_y + (mbase + r) * CDIM + kb + c4 * 4);
            uint4 u = { f2tf(v.x), f2tf(v.y), f2tf(v.z), f2tf(v.w) };
            *(uint4*)&As[r * 36 + c4 * 4] = u;
        }
        #pragma unroll
        for (int it = 0; it < 4; ++it) {
            int idx = tid + it * 256;              // 0..1023
            int r = idx >> 5, c4 = idx & 31;       // 32 float4 per k-row
            float4 v = *(const float4*)(Wp + (kb + r) * CDIM + nblk * 128 + c4 * 4);
            uint4 u = { f2tf(v.x), f2tf(v.y), f2tf(v.z), f2tf(v.w) };
            *(uint4*)&Bs[r * 136 + c4 * 4] = u;
        }
        __syncthreads();

        #pragma unroll
        for (int ks = 0; ks < TK; ks += 8) {
            unsigned a[2][4], b[8][2];
            #pragma unroll
            for (int mt = 0; mt < 2; mt++) {
                int base = (rb + mt * 16 + g) * 36 + ks + tg;
                a[mt][0] = As[base];
                a[mt][1] = As[base + 8 * 36];
                a[mt][2] = As[base + 4];
                a[mt][3] = As[base + 8 * 36 + 4];
            }
            #pragma unroll
            for (int nt = 0; nt < 8; nt++) {
                int col = cb + nt * 8 + g;
                b[nt][0] = Bs[(ks + tg) * 136 + col];
                b[nt][1] = Bs[(ks + tg + 4) * 136 + col];
            }
            #pragma unroll
            for (int mt = 0; mt < 2; mt++)
                #pragma unroll
                for (int nt = 0; nt < 8; nt++)
                    mma_tf32(acc[mt][nt], a[mt], b[nt]);
        }
        __syncthreads();
    }

    // Epilogue: bias + store (float2 per fragment row)
    #pragma unroll
    for (int mt = 0; mt < 2; mt++)
        #pragma unroll
        for (int nt = 0; nt < 8; nt++) {
            int c = cb + nt * 8 + tg * 2;
            float b0 = bp[nblk * 128 + c];
            float b1 = bp[nblk * 128 + c + 1];
            #pragma unroll
            for (int half = 0; half < 2; half++) {
                int r = rb + mt * 16 + g + half * 8;
                float2 o;
                o.x = acc[mt][nt][half * 2 + 0] + b0;
                o.y = acc[mt][nt][half * 2 + 1] + b1;
                *(float2*)(out + (mbase + r) * CDIM + nblk * 128 + c) = o;
            }
        }
}

// ---------------------------------------------------------------------------
extern "C" void kernel_launch(void* const* d_in, const int* in_sizes, int n_in,
                              void* d_out, int out_size)
{
    const float* x     = (const float*)d_in[0];
    const float* Wqkv  = (const float*)d_in[1];
    const float* Wproj = (const float*)d_in[2];
    const float* bproj = (const float*)d_in[3];
    float* out = (float*)d_out;

    dim3 g1(HN, MROWS / TM);           // (8, 640)
    k1_qkv<<<g1, 256>>>(x, Wqkv);

    dim3 g2(NBATCH, HN);               // (4, 8)
    k_reduce<<<g2, 1024>>>();

    k2_y<<<MROWS / 256, 256>>>();      // 320 blocks

    dim3 g3(MROWS / TM, 2);            // (640, 2)
    k3_proj<<<g3, 256>>>(Wproj, bproj, out);
}

// round 4
// speedup vs baseline: 2.3690x; 1.1309x over previous
#include <cuda_runtime.h>
#include <math.h>

// Problem constants
#define MROWS 81920          // BV*HW = 20*4096  (== B*L = 4*20480)
#define CDIM  256
#define LB    20480          // rows per batch n
#define HN    8
#define DH    32
#define NBATCH 4
#define TILES 160            // L-tiles of 128 per batch
#define TM 128
#define TK 32

// Scratch (static __device__ — no allocation allowed)
__device__ float g_q   [MROWS * CDIM];                  // elu(q)+1
__device__ float g_kvp [NBATCH * TILES * HN * DH * DH]; // per-tile kv partials
__device__ float g_ksp [NBATCH * TILES * HN * DH];      // per-tile k_sum partials
__device__ float g_ksum[NBATCH * HN * DH];
__device__ float g_P   [NBATCH * CDIM * CDIM];          // P_n = kv^T @ W_proj

__device__ __forceinline__ unsigned f2tf(float f) {
    unsigned u;
    asm("cvt.rna.tf32.f32 %0, %1;" : "=r"(u) : "f"(f));
    return u;
}

__device__ __forceinline__ void mma_tf32(float* c, const unsigned* a, const unsigned* b) {
    asm volatile(
        "mma.sync.aligned.m16n8k8.row.col.f32.tf32.tf32.f32 "
        "{%0,%1,%2,%3}, {%4,%5,%6,%7}, {%8,%9}, {%0,%1,%2,%3};\n"
        : "+f"(c[0]), "+f"(c[1]), "+f"(c[2]), "+f"(c[3])
        : "r"(a[0]), "r"(a[1]), "r"(a[2]), "r"(a[3]), "r"(b[0]), "r"(b[1]));
}

// ---------------------------------------------------------------------------
// k1 tile loaders (global -> tf32 -> smem buffer)
// ---------------------------------------------------------------------------
__device__ __forceinline__ void k1_load(const float* __restrict__ x,
                                        const float* __restrict__ Wqkv,
                                        unsigned* Ab, unsigned* Bb,
                                        long mbase, int h, int kb, int tid)
{
    #pragma unroll
    for (int it = 0; it < 4; ++it) {
        int idx = tid + it * 256;              // 0..1023
        int r = idx >> 3, c4 = idx & 7;
        float4 v = *(const float4*)(x + (mbase + r) * CDIM + kb + c4 * 4);
        uint4 u = { f2tf(v.x), f2tf(v.y), f2tf(v.z), f2tf(v.w) };
        *(uint4*)&Ab[r * 36 + c4 * 4] = u;
    }
    #pragma unroll
    for (int it = 0; it < 3; ++it) {
        int idx = tid + it * 256;              // 0..767
        int r = idx / 24, c4 = idx % 24;
        int j = c4 * 4;
        int part = j >> 5, jj = j & 31;
        float4 v = *(const float4*)(Wqkv + (kb + r) * 768 + part * 256 + h * 32 + jj);
        uint4 u = { f2tf(v.x), f2tf(v.y), f2tf(v.z), f2tf(v.w) };
        *(uint4*)&Bb[r * 104 + j] = u;
    }
}

// ---------------------------------------------------------------------------
// k1: per (head, L-tile of 128 rows): qkv GEMM slice (128 x 96) via TF32 MMA
//     with double-buffered smem; elu+1 on q,k; q -> g_q; per-tile kv and
//     k_sum partials.
// ---------------------------------------------------------------------------
__global__ __launch_bounds__(256, 2) void k1_qkv(const float* __restrict__ x,
                                                 const float* __restrict__ Wqkv)
{
    extern __shared__ float sm[];                   // 63488 B
    unsigned* As = (unsigned*)sm;                   // [2][128*36]
    unsigned* Bs = (unsigned*)(sm + 9216);          // [2][32*104]

    const int h    = blockIdx.x;        // 0..7
    const int tile = blockIdx.y;        // 0..639
    const int tid  = threadIdx.x;
    const int warp = tid >> 5, lane = tid & 31;
    const int wm = warp >> 1, wn = warp & 1;        // 4 x 2 warp grid
    const int rb = wm * 32, cb = wn * 48;           // warp tile 32 x 48
    const int g  = lane >> 2, tg = lane & 3;
    const long mbase = (long)tile * TM;

    float acc[2][6][4];
    #pragma unroll
    for (int mt = 0; mt < 2; mt++)
        #pragma unroll
        for (int nt = 0; nt < 6; nt++)
            #pragma unroll
            for (int e = 0; e < 4; e++) acc[mt][nt][e] = 0.f;

    // Prologue: tile 0 into buffer 0
    k1_load(x, Wqkv, As, Bs, mbase, h, 0, tid);
    __syncthreads();

    for (int i = 0; i < 8; i++) {
        int cur = i & 1;
        if (i < 7)
            k1_load(x, Wqkv, As + (cur ^ 1) * 4608, Bs + (cur ^ 1) * 3328,
                    mbase, h, (i + 1) * TK, tid);

        unsigned* Ac = As + cur * 4608;
        unsigned* Bc = Bs + cur * 3328;
        #pragma unroll
        for (int ks = 0; ks < TK; ks += 8) {
            unsigned a[2][4], b[6][2];
            #pragma unroll
            for (int mt = 0; mt < 2; mt++) {
                int base = (rb + mt * 16 + g) * 36 + ks + tg;
                a[mt][0] = Ac[base];
                a[mt][1] = Ac[base + 8 * 36];
                a[mt][2] = Ac[base + 4];
                a[mt][3] = Ac[base + 8 * 36 + 4];
            }
            #pragma unroll
            for (int nt = 0; nt < 6; nt++) {
                int col = cb + nt * 8 + g;
                b[nt][0] = Bc[(ks + tg) * 104 + col];
                b[nt][1] = Bc[(ks + tg + 4) * 104 + col];
            }
            #pragma unroll
            for (int mt = 0; mt < 2; mt++)
                #pragma unroll
                for (int nt = 0; nt < 6; nt++)
                    mma_tf32(acc[mt][nt], a[mt], b[nt]);
        }
        __syncthreads();
    }

    // Epilogue: elu+1 on q,k; q -> global; k,v -> smem (reuse, post-sync)
    float* ksm = sm;            // [128][32]
    float* vsm = sm + 4096;     // [128][32]
    #pragma unroll
    for (int mt = 0; mt < 2; mt++)
        #pragma unroll
        for (int nt = 0; nt < 6; nt++)
            #pragma unroll
            for (int e = 0; e < 4; e++) {
                int r = rb + mt * 16 + g + ((e >= 2) ? 8 : 0);
                int c = cb + nt * 8 + tg * 2 + (e & 1);
                float val = acc[mt][nt][e];
                int part = c >> 5, jj = c & 31;
                if (part == 0) {
                    val = (val > 0.f) ? (val + 1.f) : expf(val);
                    g_q[(mbase + r) * CDIM + h * 32 + jj] = val;
                } else if (part == 1) {
                    val = (val > 0.f) ? (val + 1.f) : expf(val);
                    ksm[r * 32 + jj] = val;
                } else {
                    vsm[r * 32 + jj] = val;
                }
            }
    __syncthreads();

    // Partial kv[m][d] = sum_l vsm[l][m] * ksm[l][d]
    const int m  = tid >> 3;
    const int dd = (tid & 7) * 4;
    float s0 = 0.f, s1 = 0.f, s2 = 0.f, s3 = 0.f;
    for (int l = 0; l < 128; l++) {
        float  vv = vsm[l * 32 + m];
        float4 k4 = *(const float4*)&ksm[l * 32 + dd];
        s0 += vv * k4.x; s1 += vv * k4.y; s2 += vv * k4.z; s3 += vv * k4.w;
    }
    long pb = (((long)tile * HN + h) * DH + m) * DH + dd;
    g_kvp[pb] = s0; g_kvp[pb + 1] = s1; g_kvp[pb + 2] = s2; g_kvp[pb + 3] = s3;

    if (tid < 32) {
        float s = 0.f;
        for (int l = 0; l < 128; l++) s += ksm[l * 32 + tid];
        g_ksp[((long)tile * HN + h) * DH + tid] = s;
    }
}

// ---------------------------------------------------------------------------
// k_reduceP: fixed-order reduction of kv/k_sum partials per (n,h), then
//            P[n][h*32+d][j] = sum_m kv[m][d] * Wp[h*32+m][j]  (fp32 exact)
// ---------------------------------------------------------------------------
__global__ __launch_bounds__(1024) void k_reduceP(const float* __restrict__ Wp)
{
    __shared__ float kvs[1024];
    const int n = blockIdx.x, h = blockIdx.y;
    const int tid = threadIdx.x;  // 0..1023 (= m*32+d)
    float s = 0.f;
    for (int t = 0; t < TILES; t++)
        s += g_kvp[(((long)(n * TILES + t) * HN + h) * 1024) + tid];
    kvs[tid] = s;
    if (tid < 32) {
        float s2 = 0.f;
        for (int t = 0; t < TILES; t++)
            s2 += g_ksp[((long)(n * TILES + t) * HN + h) * 32 + tid];
        g_ksum[(n * HN + h) * 32 + tid] = s2;
    }
    __syncthreads();

    const int j  = tid & 255;
    const int d0 = (tid >> 8) * 8;
    float w[32];
    #pragma unroll
    for (int m = 0; m < 32; m++) w[m] = Wp[(h * 32 + m) * CDIM + j];
    #pragma unroll
    for (int dd = 0; dd < 8; dd++) {
        int d = d0 + dd;
        float p = 0.f;
        #pragma unroll
        for (int m = 0; m < 32; m++) p += kvs[m * 32 + d] * w[m];
        g_P[((long)n * CDIM + h * 32 + d) * CDIM + j] = p;
    }
}

// ---------------------------------------------------------------------------
// k3 tile loaders
// ---------------------------------------------------------------------------
__device__ __forceinline__ void k3_loadA(unsigned* Ab, long mbase, int n,
                                         int kb, int tid)
{
    const int h = kb >> 5, c4 = tid & 7;
    float4 ks4 = *(const float4*)(g_ksum + (n * HN + h) * 32 + c4 * 4);
    #pragma unroll
    for (int it = 0; it < 4; ++it) {
        int idx = tid + it * 256;
        int r = idx >> 3;
        float4 v = *(const float4*)(g_q + (mbase + r) * CDIM + kb + c4 * 4);
        float pd = v.x * ks4.x + v.y * ks4.y + v.z * ks4.z + v.w * ks4.w;
        pd += __shfl_xor_sync(0xffffffffu, pd, 1);
        pd += __shfl_xor_sync(0xffffffffu, pd, 2);
        pd += __shfl_xor_sync(0xffffffffu, pd, 4);
        float z = 1.f / (pd + 1e-6f);
        uint4 u = { f2tf(v.x * z), f2tf(v.y * z), f2tf(v.z * z), f2tf(v.w * z) };
        *(uint4*)&Ab[r * 36 + c4 * 4] = u;
    }
}

__device__ __forceinline__ void k3_loadB(const float* __restrict__ Pn,
                                         unsigned* Bb, int nblk, int kb, int tid)
{
    #pragma unroll
    for (int it = 0; it < 4; ++it) {
        int idx = tid + it * 256;
        int r = idx >> 5, c4 = idx & 31;
        float4 v = *(const float4*)(Pn + (kb + r) * CDIM + nblk * 128 + c4 * 4);
        uint4 u = { f2tf(v.x), f2tf(v.y), f2tf(v.z), f2tf(v.w) };
        *(uint4*)&Bb[r * 136 + c4 * 4] = u;
    }
}

// ---------------------------------------------------------------------------
// k3: out = (z .* q) @ P_n + b_proj via TF32 MMA, double-buffered.
//     Grid (640, 2), block 256, block tile 128 x 128.
// ---------------------------------------------------------------------------
__global__ __launch_bounds__(256) void k3_proj(const float* __restrict__ bp,
                                               float* __restrict__ out)
{
    extern __shared__ float sm[];                   // 71680 B
    unsigned* As = (unsigned*)sm;                   // [2][128*36]
    unsigned* Bs = (unsigned*)(sm + 9216);          // [2][32*136]

    const int tile = blockIdx.x;   // 0..639
    const int nblk = blockIdx.y;   // 0..1
    const int n    = tile / TILES;
    const float* Pn = g_P + (long)n * CDIM * CDIM;
    const int tid  = threadIdx.x;
    const int warp = tid >> 5, lane = tid & 31;
    const int wm = warp >> 1, wn = warp & 1;
    const int rb = wm * 32, cb = wn * 64;
    const int g  = lane >> 2, tg = lane & 3;
    const long mbase = (long)tile * TM;

    float acc[2][8][4];
    #pragma unroll
    for (int mt = 0; mt < 2; mt++)
        #pragma unroll
        for (int nt = 0; nt < 8; nt++)
            #pragma unroll
            for (int e = 0; e < 4; e++) acc[mt][nt][e] = 0.f;

    k3_loadA(As, mbase, n, 0, tid);
    k3_loadB(Pn, Bs, nblk, 0, tid);
    __syncthreads();

    for (int i = 0; i < 8; i++) {
        int cur = i & 1;
        if (i < 7) {
            k3_loadA(As + (cur ^ 1) * 4608, mbase, n, (i + 1) * TK, tid);
            k3_loadB(Pn, Bs + (cur ^ 1) * 4352, nblk, (i + 1) * TK, tid);
        }
        unsigned* Ac = As + cur * 4608;
        unsigned* Bc = Bs + cur * 4352;
        #pragma unroll
        for (int ks = 0; ks < TK; ks += 8) {
            unsigned a[2][4], b[8][2];
            #pragma unroll
            for (int mt = 0; mt < 2; mt++) {
                int base = (rb + mt * 16 + g) * 36 + ks + tg;
                a[mt][0] = Ac[base];
                a[mt][1] = Ac[base + 8 * 36];
                a[mt][2] = Ac[base + 4];
                a[mt][3] = Ac[base + 8 * 36 + 4];
            }
            #pragma unroll
            for (int nt = 0; nt < 8; nt++) {
                int col = cb + nt * 8 + g;
                b[nt][0] = Bc[(ks + tg) * 136 + col];
                b[nt][1] = Bc[(ks + tg + 4) * 136 + col];
            }
            #pragma unroll
            for (int mt = 0; mt < 2; mt++)
                #pragma unroll
                for (int nt = 0; nt < 8; nt++)
                    mma_tf32(acc[mt][nt], a[mt], b[nt]);
        }
        __syncthreads();
    }

    // Epilogue: bias + store
    #pragma unroll
    for (int mt = 0; mt < 2; mt++)
        #pragma unroll
        for (int nt = 0; nt < 8; nt++) {
            int c = cb + nt * 8 + tg * 2;
            float b0 = bp[nblk * 128 + c];
            float b1 = bp[nblk * 128 + c + 1];
            #pragma unroll
            for (int half = 0; half < 2; half++) {
                int r = rb + mt * 16 + g + half * 8;
                float2 o;
                o.x = acc[mt][nt][half * 2 + 0] + b0;
                o.y = acc[mt][nt][half * 2 + 1] + b1;
                *(float2*)(out + (mbase + r) * CDIM + nblk * 128 + c) = o;
            }
        }
}

// ---------------------------------------------------------------------------
extern "C" void kernel_launch(void* const* d_in, const int* in_sizes, int n_in,
                              void* d_out, int out_size)
{
    const float* x     = (const float*)d_in[0];
    const float* Wqkv  = (const float*)d_in[1];
    const float* Wproj = (const float*)d_in[2];
    const float* bproj = (const float*)d_in[3];
    float* out = (float*)d_out;

    cudaFuncSetAttribute(k1_qkv,  cudaFuncAttributeMaxDynamicSharedMemorySize, 63488);
    cudaFuncSetAttribute(k3_proj, cudaFuncAttributeMaxDynamicSharedMemorySize, 71680);

    dim3 g1(HN, MROWS / TM);           // (8, 640)
    k1_qkv<<<g1, 256, 63488>>>(x, Wqkv);

    dim3 g2(NBATCH, HN);               // (4, 8)
    k_reduceP<<<g2, 1024>>>(Wproj);

    dim3 g3(MROWS / TM, 2);            // (640, 2)
    k3_proj<<<g3, 256, 71680>>>(bproj, out);
}